// round 4
// baseline (speedup 1.0000x reference)
#include <cuda_runtime.h>
#include <cstdint>

#define BB 4
#define NN 8192
#define MM 8192
// block: 16(tx) x 8(ty) = 128 threads
// n-tile per block: 128  (n = nbase + i*16 + tx, i<8; packed as 4 f32x2 pairs)
// m processed in tiles of 64 per iteration (m = mt + j*8 + ty, j<8)
// each block covers an M-chunk of 1024 -> 16 iterations
#define GRIDN (NN/128)     // 64
#define GRIDM 8            // M chunks of 1024
#define MCHUNK (MM/GRIDM)  // 1024

typedef unsigned long long ull;

__device__ int g_d1min[BB*NN];
__device__ int g_d2min[BB*MM];

__device__ __forceinline__ ull pk2(float lo, float hi) {
    ull r; asm("mov.b64 %0, {%1, %2};" : "=l"(r) : "f"(lo), "f"(hi)); return r;
}
__device__ __forceinline__ void upk2(ull v, float& lo, float& hi) {
    asm("mov.b64 {%0, %1}, %2;" : "=f"(lo), "=f"(hi) : "l"(v));
}
__device__ __forceinline__ ull fma2(ull a, ull b, ull c) {
    ull d; asm("fma.rn.f32x2 %0, %1, %2, %3;" : "=l"(d) : "l"(a), "l"(b), "l"(c)); return d;
}
__device__ __forceinline__ ull add2(ull a, ull b) {
    ull d; asm("add.rn.f32x2 %0, %1, %2;" : "=l"(d) : "l"(a), "l"(b)); return d;
}

__global__ void init_kernel(float* out) {
    int idx = blockIdx.x * blockDim.x + threadIdx.x;
    if (idx < BB*NN) g_d1min[idx] = 0x7F7FFFFF;   // FLT_MAX bits
    if (idx < BB*MM) g_d2min[idx] = 0x7F7FFFFF;
    if (idx == 0) out[0] = 0.0f;
}

__global__ __launch_bounds__(128)
void chamfer_kernel(const float* __restrict__ p1, const float* __restrict__ p2) {
    const int tx = threadIdx.x & 15;
    const int ty = threadIdx.x >> 4;
    const int b  = blockIdx.z;
    const int nbase  = blockIdx.x * 128;
    const int mchunk = blockIdx.y * MCHUNK;

    // m-tile, pre-duplicated: per m-point {x,x},{y,y},{z,z},{w,w} (w = 0.5*|b|^2)
    __shared__ ull   sh2[64 * 4];
    __shared__ float dsh[64 * 17];   // reused: d2 tile reduce, then d1 final reduce

    // Load this thread's 8 n-points as 4 packed f32x2 pairs.
    // Pair ip holds n-points i=2*ip and i=2*ip+1, n_i = nbase + i*16 + tx.
    ull PNX[4], PNY[4], PNZ[4], PHN[4];
    float d1[8];
#pragma unroll
    for (int ip = 0; ip < 4; ip++) {
        const float* pa = p1 + ((size_t)b * NN + nbase + (2*ip)  *16 + tx) * 3;
        const float* pb = p1 + ((size_t)b * NN + nbase + (2*ip+1)*16 + tx) * 3;
        float xa = pa[0], ya = pa[1], za = pa[2];
        float xb = pb[0], yb = pb[1], zb = pb[2];
        PNX[ip] = pk2(-xa, -xb);
        PNY[ip] = pk2(-ya, -yb);
        PNZ[ip] = pk2(-za, -zb);
        PHN[ip] = pk2(0.5f*(xa*xa + ya*ya + za*za), 0.5f*(xb*xb + yb*yb + zb*zb));
        d1[2*ip] = 3.0e38f; d1[2*ip+1] = 3.0e38f;
    }

    for (int it = 0; it < MCHUNK/64; it++) {
        const int mt = mchunk + it * 64;
        __syncthreads();   // protect sh2/dsh reuse from previous iteration readers
        if (threadIdx.x < 64) {
            const float* p = p2 + ((size_t)b * MM + mt + threadIdx.x) * 3;
            float x = p[0], y = p[1], z = p[2];
            float w = 0.5f * (x*x + y*y + z*z);
            ull* s = &sh2[threadIdx.x * 4];
            s[0] = pk2(x, x); s[1] = pk2(y, y); s[2] = pk2(z, z); s[3] = pk2(w, w);
        }
        __syncthreads();

        float d2p[8];
#pragma unroll
        for (int j = 0; j < 8; j++) {
            const ull* q = &sh2[(j*8 + ty) * 4];
            ull qx = q[0], qy = q[1], qz = q[2], qw = q[3];
            float dm0 = 3.0e38f, dm1 = 3.0e38f;
#pragma unroll
            for (int ip = 0; ip < 4; ip++) {
                // t = 0.5|a|^2 + 0.5|b|^2 - a.b  (two n-points per packed op)
                ull t = fma2(PNX[ip], qx, PHN[ip]);
                t = fma2(PNY[ip], qy, t);
                t = fma2(PNZ[ip], qz, t);
                t = add2(t, qw);
                float t0, t1; upk2(t, t0, t1);
                d1[2*ip]   = fminf(d1[2*ip],   t0);
                d1[2*ip+1] = fminf(d1[2*ip+1], t1);
                dm0 = fminf(dm0, t0);
                dm1 = fminf(dm1, t1);
            }
            d2p[j] = fminf(dm0, dm1);
        }

        // reduce d2 partials across tx (16 threads per m)
#pragma unroll
        for (int j = 0; j < 8; j++) dsh[(ty*8 + j)*17 + tx] = d2p[j];
        __syncthreads();
        if (threadIdx.x < 64) {
            float v = dsh[threadIdx.x * 17];
#pragma unroll
            for (int k = 1; k < 16; k++) v = fminf(v, dsh[threadIdx.x*17 + k]);
            v = fmaxf(v, 0.0f);  // squared dist >= 0 up to rounding; ref clamps
            atomicMin(&g_d2min[b*MM + mt + threadIdx.x], __float_as_int(v));
        }
    }

    // reduce d1 partials across ty (8 threads per n)
    __syncthreads();
#pragma unroll
    for (int i = 0; i < 8; i++) dsh[ty*136 + i*16 + tx] = d1[i];
    __syncthreads();
    {
        int nl = threadIdx.x;  // 0..127
        float v = dsh[nl];
#pragma unroll
        for (int k = 1; k < 8; k++) v = fminf(v, dsh[k*136 + nl]);
        v = fmaxf(v, 0.0f);
        atomicMin(&g_d1min[b*NN + nbase + nl], __float_as_int(v));
    }
}

__global__ void reduce_kernel(float* out) {
    const int total = BB*NN + BB*MM;  // 65536
    float v = 0.0f;
    for (int idx = blockIdx.x * blockDim.x + threadIdx.x; idx < total;
         idx += gridDim.x * blockDim.x) {
        int bits = (idx < BB*NN) ? g_d1min[idx] : g_d2min[idx - BB*NN];
        v += __int_as_float(bits);   // clamped min of t; dist = 2t
    }
    for (int o = 16; o > 0; o >>= 1) v += __shfl_down_sync(0xffffffffu, v, o);
    __shared__ float ws[32];
    int lane = threadIdx.x & 31, wid = threadIdx.x >> 5;
    if (lane == 0) ws[wid] = v;
    __syncthreads();
    if (wid == 0) {
        int nw = (blockDim.x + 31) >> 5;
        v = (lane < nw) ? ws[lane] : 0.0f;
        for (int o = 16; o > 0; o >>= 1) v += __shfl_down_sync(0xffffffffu, v, o);
        if (lane == 0) {
            // mean(d1)+mean(d2) = (sum1+sum2)*2 / (B*N)  [N==M]
            atomicAdd(out, v * (2.0f / (float)(BB*NN)));
        }
    }
}

extern "C" void kernel_launch(void* const* d_in, const int* in_sizes, int n_in,
                              void* d_out, int out_size) {
    const float* p1 = (const float*)d_in[0];
    const float* p2 = (const float*)d_in[1];
    float* out = (float*)d_out;
    (void)in_sizes; (void)n_in; (void)out_size;

    init_kernel<<<(BB*NN + 255)/256, 256>>>(out);
    dim3 grid(GRIDN, GRIDM, BB);
    chamfer_kernel<<<grid, 128>>>(p1, p2);
    reduce_kernel<<<64, 256>>>(out);
}

// round 5
// speedup vs baseline: 1.4511x; 1.4511x over previous
#include <cuda_runtime.h>
#include <cstdint>

#define BB 4
#define NN 8192
#define MM 8192
// Work unit: (b, nchunk, mchunk): 128 n-points x 1024 m-points.
// units = 4 * 64 * 8 = 2048.  Grid = 1216 (152 SMs x 8 blocks), each block
// loops u = bid, bid+1216  -> per-SM load evens out (13-14 units/SM).
#define NCHUNKS 64
#define MCHUNKS 8
#define UNITS (BB*NCHUNKS*MCHUNKS)   // 2048
#define GRIDB 1216
#define MCHUNK (MM/MCHUNKS)          // 1024

// Disjoint-slot partial-min scratch (written every launch before being read;
// no initialization required).
__device__ float g_d2part[NCHUNKS * BB * MM];   // [nc][b][m]   8 MB
__device__ float g_d1part[MCHUNKS * BB * NN];   // [mc][b][n]   1 MB
__device__ float g_bsum[64];

__global__ __launch_bounds__(128, 8)
void chamfer_kernel(const float* __restrict__ p1, const float* __restrict__ p2) {
    const int tx = threadIdx.x & 15;
    const int ty = threadIdx.x >> 4;

    __shared__ float4 shm[64];
    __shared__ float  dsh[64 * 17];   // reused: per-tile d2 reduce, then d1 reduce

    for (int u = blockIdx.x; u < UNITS; u += GRIDB) {
        const int b  = u >> 9;               // u / (NCHUNKS*MCHUNKS)
        const int nc = (u >> 3) & 63;
        const int mc = u & 7;
        const int nbase  = nc * 128;
        const int mchunk = mc * MCHUNK;

        // Load this thread's 8 n-points; negated coords + half-norm.
        float nx[8], ny[8], nz[8], hn[8], d1[8];
#pragma unroll
        for (int i = 0; i < 8; i++) {
            const float* p = p1 + ((size_t)b * NN + nbase + i*16 + tx) * 3;
            float x = p[0], y = p[1], z = p[2];
            nx[i] = -x; ny[i] = -y; nz[i] = -z;
            hn[i] = 0.5f * (x*x + y*y + z*z);
            d1[i] = 3.0e38f;
        }

        for (int it = 0; it < MCHUNK/64; it++) {
            const int mt = mchunk + it * 64;
            __syncthreads();   // protect shm/dsh reuse from previous readers
            if (threadIdx.x < 64) {
                const float* p = p2 + ((size_t)b * MM + mt + threadIdx.x) * 3;
                float x = p[0], y = p[1], z = p[2];
                shm[threadIdx.x] = make_float4(x, y, z, 0.5f*(x*x + y*y + z*z));
            }
            __syncthreads();

            float d2p[8];
#pragma unroll
            for (int j = 0; j < 8; j++) {
                float4 q = shm[j*8 + ty];
                float dm = 3.0e38f;
#pragma unroll
                for (int i = 0; i < 8; i++) {
                    // t = 0.5|a|^2 + 0.5|b|^2 - a.b ; squared dist = 2t
                    float t = fmaf(nx[i], q.x, hn[i]);
                    t = fmaf(ny[i], q.y, t);
                    t = fmaf(nz[i], q.z, t);
                    t = t + q.w;
                    d1[i] = fminf(d1[i], t);
                    dm    = fminf(dm, t);
                }
                d2p[j] = dm;
            }

            // reduce d2 partials across tx (16 threads per m), plain store
#pragma unroll
            for (int j = 0; j < 8; j++) dsh[(ty*8 + j)*17 + tx] = d2p[j];
            __syncthreads();
            if (threadIdx.x < 64) {
                float v = dsh[threadIdx.x * 17];
#pragma unroll
                for (int k = 1; k < 16; k++) v = fminf(v, dsh[threadIdx.x*17 + k]);
                g_d2part[(size_t)nc * (BB*MM) + b*MM + mt + threadIdx.x] = v;
            }
        }

        // reduce d1 partials across ty (8 threads per n), plain store
        __syncthreads();
#pragma unroll
        for (int i = 0; i < 8; i++) dsh[ty*136 + i*16 + tx] = d1[i];
        __syncthreads();
        {
            int nl = threadIdx.x;  // 0..127
            float v = dsh[nl];
#pragma unroll
            for (int k = 1; k < 8; k++) v = fminf(v, dsh[k*136 + nl]);
            g_d1part[(size_t)mc * (BB*NN) + b*NN + nbase + nl] = v;
        }
        // next unit's first __syncthreads() protects dsh reuse
    }
}

__global__ __launch_bounds__(256)
void reduce1_kernel() {
    const int t = blockIdx.x * blockDim.x + threadIdx.x;  // 64*256 = 16384
    float s = 0.0f;
    // d2: min over 64 n-chunks per (b,m)
    for (int idx = t; idx < BB*MM; idx += 16384) {
        float v = g_d2part[idx];
#pragma unroll 8
        for (int nc = 1; nc < NCHUNKS; nc++)
            v = fminf(v, g_d2part[(size_t)nc * (BB*MM) + idx]);
        s += fmaxf(v, 0.0f);
    }
    // d1: min over 8 m-chunks per (b,n)
    for (int idx = t; idx < BB*NN; idx += 16384) {
        float v = g_d1part[idx];
#pragma unroll
        for (int mcx = 1; mcx < MCHUNKS; mcx++)
            v = fminf(v, g_d1part[(size_t)mcx * (BB*NN) + idx]);
        s += fmaxf(v, 0.0f);
    }
    // block reduce
    for (int o = 16; o > 0; o >>= 1) s += __shfl_down_sync(0xffffffffu, s, o);
    __shared__ float ws[8];
    int lane = threadIdx.x & 31, wid = threadIdx.x >> 5;
    if (lane == 0) ws[wid] = s;
    __syncthreads();
    if (wid == 0) {
        s = (lane < 8) ? ws[lane] : 0.0f;
        for (int o = 4; o > 0; o >>= 1) s += __shfl_down_sync(0xffffffffu, s, o);
        if (lane == 0) g_bsum[blockIdx.x] = s;
    }
}

__global__ void reduce2_kernel(float* out) {
    // single warp: sum 64 block partials, write final (no atomics, no init)
    int lane = threadIdx.x;  // 32 threads
    float s = g_bsum[lane] + g_bsum[lane + 32];
    for (int o = 16; o > 0; o >>= 1) s += __shfl_down_sync(0xffffffffu, s, o);
    if (lane == 0) {
        // stored values are t = d/2 ; mean(d1)+mean(d2) = 2*sum / (B*N) [N==M]
        out[0] = s * (2.0f / (float)(BB*NN));
    }
}

extern "C" void kernel_launch(void* const* d_in, const int* in_sizes, int n_in,
                              void* d_out, int out_size) {
    const float* p1 = (const float*)d_in[0];
    const float* p2 = (const float*)d_in[1];
    float* out = (float*)d_out;
    (void)in_sizes; (void)n_in; (void)out_size;

    chamfer_kernel<<<GRIDB, 128>>>(p1, p2);
    reduce1_kernel<<<64, 256>>>();
    reduce2_kernel<<<1, 32>>>(out);
}

// round 7
// speedup vs baseline: 1.5627x; 1.0769x over previous
#include <cuda_runtime.h>
#include <cstdint>

#define BB 4
#define NN 8192
#define MM 8192
// Block = work unit: (b, nc, mc) -> 128 n-points x 512 m-points.
// Grid = 64 x 16 x 4 = 4096 blocks, non-persistent (scheduler backfills).
// Block: 16(tx) x 8(ty) = 128 threads; m-tiles of 128 (j<16), 4 tiles/unit.
#define NCHUNKS 64
#define MCHUNKS 16
#define MCHUNK (MM/MCHUNKS)   // 512
#define TILES  (MCHUNK/128)   // 4

// Disjoint-slot partial-min scratch; fully written every launch before read,
// so no initialization kernel is needed.
__device__ float g_d2part[NCHUNKS * BB * MM];   // [nc][b][m]  8 MB
__device__ float g_d1part[MCHUNKS * BB * NN];   // [mc][b][n]  2 MB
__device__ float g_bsum[128];

__global__ __launch_bounds__(128, 8)
void chamfer_kernel(const float* __restrict__ p1, const float* __restrict__ p2) {
    const int tid = threadIdx.x;
    const int tx  = tid & 15;
    const int ty  = tid >> 4;
    const int nc  = blockIdx.x;
    const int mc  = blockIdx.y;
    const int b   = blockIdx.z;
    const int nbase = nc * 128;
    const int mbase = mc * MCHUNK;

    __shared__ float4 shm[2][128];        // m-tile: {x,y,z, 0.5*|b|^2}
    __shared__ float  dsh[2][128 * 17];   // d2 cross-tx scratch (dbl-buffered)

    // This thread's 8 n-points: negated coords + half-norm.
    float nx[8], ny[8], nz[8], hn[8], d1[8];
#pragma unroll
    for (int i = 0; i < 8; i++) {
        const float* p = p1 + ((size_t)b * NN + nbase + i*16 + tx) * 3;
        float x = p[0], y = p[1], z = p[2];
        nx[i] = -x; ny[i] = -y; nz[i] = -z;
        hn[i] = 0.5f * (x*x + y*y + z*z);
        d1[i] = 3.0e38f;
    }

    // preload tile 0 (all 128 threads, one m-point each)
    {
        const float* p = p2 + ((size_t)b * MM + mbase + tid) * 3;
        float x = p[0], y = p[1], z = p[2];
        shm[0][tid] = make_float4(x, y, z, 0.5f*(x*x + y*y + z*z));
    }
    __syncthreads();

    for (int it = 0; it < TILES; it++) {
        const int cur = it & 1;

        // prefetch next tile into registers (overlaps with compute)
        float rx = 0.f, ry = 0.f, rz = 0.f;
        if (it < TILES-1) {
            const float* p = p2 + ((size_t)b * MM + mbase + (it+1)*128 + tid) * 3;
            rx = p[0]; ry = p[1]; rz = p[2];
        }

        float d2p[16];
#pragma unroll
        for (int j = 0; j < 16; j++) {
            float4 q = shm[cur][j*8 + ty];
            float ts[8];
#pragma unroll
            for (int i = 0; i < 8; i++) {
                // t = 0.5|a|^2 + 0.5|b|^2 - a.b ; squared dist = 2t
                float t = fmaf(nx[i], q.x, hn[i]);
                t = fmaf(ny[i], q.y, t);
                t = fmaf(nz[i], q.z, t);
                t = t + q.w;
                d1[i] = fminf(d1[i], t);
                ts[i] = t;
            }
            // balanced tree min (depth 3)
            float a0 = fminf(ts[0], ts[1]), a1 = fminf(ts[2], ts[3]);
            float a2 = fminf(ts[4], ts[5]), a3 = fminf(ts[6], ts[7]);
            d2p[j] = fminf(fminf(a0, a1), fminf(a2, a3));
        }

        // stage d2 partials (slot s = j*8+ty <-> m = tile_base + s)
#pragma unroll
        for (int j = 0; j < 16; j++) dsh[cur][(j*8 + ty)*17 + tx] = d2p[j];

        // store prefetched tile into the other buffer
        if (it < TILES-1) {
            shm[1-cur][tid] = make_float4(rx, ry, rz, 0.5f*(rx*rx + ry*ry + rz*rz));
        }
        __syncthreads();   // covers dsh[cur] writes + shm[1-cur] writes

        // cross-tx reduce: each thread owns one m-slot of this tile
        {
            float v = dsh[cur][tid*17];
#pragma unroll
            for (int k = 1; k < 16; k++) v = fminf(v, dsh[cur][tid*17 + k]);
            g_d2part[(size_t)nc * (BB*MM) + b*MM + mbase + it*128 + tid] = v;
        }
        // dsh[cur] rewritten at it+2; protected by it+1's barrier.
    }

    // reduce d1 partials across ty (8 threads per n)
    __syncthreads();
#pragma unroll
    for (int i = 0; i < 8; i++) dsh[0][ty*136 + i*16 + tx] = d1[i];
    __syncthreads();
    {
        float v = dsh[0][tid];
#pragma unroll
        for (int k = 1; k < 8; k++) v = fminf(v, dsh[0][k*136 + tid]);
        g_d1part[(size_t)mc * (BB*NN) + b*NN + nbase + tid] = v;
    }
}

__global__ __launch_bounds__(256)
void reduce1_kernel() {
    const int t = blockIdx.x * blockDim.x + threadIdx.x;  // 128*256 = 32768
    float s = 0.0f;
    // d2: min over 64 n-chunks per (b,m)
    for (int idx = t; idx < BB*MM; idx += 32768) {
        float v = g_d2part[idx];
#pragma unroll 8
        for (int nc = 1; nc < NCHUNKS; nc++)
            v = fminf(v, g_d2part[(size_t)nc * (BB*MM) + idx]);
        s += fmaxf(v, 0.0f);
    }
    // d1: min over 16 m-chunks per (b,n)
    for (int idx = t; idx < BB*NN; idx += 32768) {
        float v = g_d1part[idx];
#pragma unroll
        for (int mcx = 1; mcx < MCHUNKS; mcx++)
            v = fminf(v, g_d1part[(size_t)mcx * (BB*NN) + idx]);
        s += fmaxf(v, 0.0f);
    }
    // block reduce
    for (int o = 16; o > 0; o >>= 1) s += __shfl_down_sync(0xffffffffu, s, o);
    __shared__ float ws[8];
    int lane = threadIdx.x & 31, wid = threadIdx.x >> 5;
    if (lane == 0) ws[wid] = s;
    __syncthreads();
    if (wid == 0) {
        s = (lane < 8) ? ws[lane] : 0.0f;
        for (int o = 4; o > 0; o >>= 1) s += __shfl_down_sync(0xffffffffu, s, o);
        if (lane == 0) g_bsum[blockIdx.x] = s;
    }
}

__global__ void reduce2_kernel(float* out) {
    // single warp: sum 128 block partials, write final result
    int lane = threadIdx.x;  // 32 threads
    float s = g_bsum[lane] + g_bsum[lane + 32] + g_bsum[lane + 64] + g_bsum[lane + 96];
    for (int o = 16; o > 0; o >>= 1) s += __shfl_down_sync(0xffffffffu, s, o);
    if (lane == 0) {
        // stored values are t = d/2 ; mean(d1)+mean(d2) = 2*sum / (B*N) [N==M]
        out[0] = s * (2.0f / (float)(BB*NN));
    }
}

extern "C" void kernel_launch(void* const* d_in, const int* in_sizes, int n_in,
                              void* d_out, int out_size) {
    const float* p1 = (const float*)d_in[0];
    const float* p2 = (const float*)d_in[1];
    float* out = (float*)d_out;
    (void)in_sizes; (void)n_in; (void)out_size;

    dim3 grid(NCHUNKS, MCHUNKS, BB);   // 64 x 16 x 4 = 4096 blocks
    chamfer_kernel<<<grid, 128>>>(p1, p2);
    reduce1_kernel<<<128, 256>>>();
    reduce2_kernel<<<1, 32>>>(out);
}